// round 1
// baseline (speedup 1.0000x reference)
#include <cuda_runtime.h>
#include <cuda_bf16.h>
#include <cstddef>

// Problem constants
#define Bc 64
#define Sc 512
#define Hc 1024
#define Vc 32000
#define SB (Sc * Bc)          // 32768
#define NB 16                 // 1024 / 64 column blocks in attention GEMM

// ---------------- scratch (device globals, no allocation) ----------------
__device__ float g_hWh[Bc * Hc];          // hidden @ W_h^T + attn_w_b  [b, h]
__device__ float g_spart[SB * NB];        // partial scores per column-block
__device__ float g_x[Bc * 2 * Hc];        // [emb_row ; context] per b
__device__ float g_gi[3 * Hc * Bc];       // gi[j, b]
__device__ float g_gh[3 * Hc * Bc];       // gh[j, b]

// ---------------------------------------------------------------------------
// Generic NT GEMM: C = A[M x K] * B[N x K]^T, row-major A (lda), B (ldb).
// Tile 64x64, Ktile 16, 256 threads, 4x4 per thread. M, N multiples of 64,
// K multiple of 16 (always true here).
// ---------------------------------------------------------------------------
__global__ __launch_bounds__(256)
void gemm_nt_kernel(const float* __restrict__ A, int lda,
                    const float* __restrict__ B, int ldb,
                    float* __restrict__ C, int ldc,
                    int K,
                    const float* __restrict__ bias_m,
                    const float* __restrict__ bias_n,
                    int trans_store)
{
    __shared__ float As[16][68];
    __shared__ float Bs[16][68];
    const int tid = threadIdx.x;
    const int m0 = blockIdx.x * 64, n0 = blockIdx.y * 64;

    const int lrow = tid >> 2;
    const int lk   = (tid & 3) * 4;
    const float* Aptr = A + (size_t)(m0 + lrow) * lda + lk;
    const float* Bptr = B + (size_t)(n0 + lrow) * ldb + lk;

    const int ty = tid >> 4, tx = tid & 15;
    float acc[4][4] = {};

    for (int k0 = 0; k0 < K; k0 += 16) {
        float4 av = *(const float4*)(Aptr + k0);
        float4 bv = *(const float4*)(Bptr + k0);
        As[lk + 0][lrow] = av.x; As[lk + 1][lrow] = av.y;
        As[lk + 2][lrow] = av.z; As[lk + 3][lrow] = av.w;
        Bs[lk + 0][lrow] = bv.x; Bs[lk + 1][lrow] = bv.y;
        Bs[lk + 2][lrow] = bv.z; Bs[lk + 3][lrow] = bv.w;
        __syncthreads();
#pragma unroll
        for (int k = 0; k < 16; k++) {
            float4 a = *(const float4*)&As[k][ty * 4];
            float4 b = *(const float4*)&Bs[k][tx * 4];
            float ar[4] = {a.x, a.y, a.z, a.w};
            float br[4] = {b.x, b.y, b.z, b.w};
#pragma unroll
            for (int i = 0; i < 4; i++)
#pragma unroll
                for (int j = 0; j < 4; j++)
                    acc[i][j] += ar[i] * br[j];
        }
        __syncthreads();
    }

#pragma unroll
    for (int i = 0; i < 4; i++) {
        int m = m0 + ty * 4 + i;
        float bm = bias_m ? bias_m[m] : 0.0f;
#pragma unroll
        for (int j = 0; j < 4; j++) {
            int n = n0 + tx * 4 + j;
            float v = acc[i][j] + bm + (bias_n ? bias_n[n] : 0.0f);
            if (trans_store) C[(size_t)n * ldc + m] = v;
            else             C[(size_t)m * ldc + n] = v;
        }
    }
}

// ---------------------------------------------------------------------------
// Fused attention score kernel:
//   e[r, h] = enc[r, :] . We[h, :]   (r = s*B + b, We = attn_w_W[:, H:2H])
//   partial_score[r, nb] = sum_{h in col-block nb} tanh(e + hWh[b,h]) * v[h]
// Tile: 128 rows x 64 cols, Ktile 16, 256 threads, 8x4 per thread.
// ---------------------------------------------------------------------------
__global__ __launch_bounds__(256)
void attn_score_kernel(const float* __restrict__ enc,
                       const float* __restrict__ W,     // attn_w_W [H x 2H]
                       const float* __restrict__ vvec)  // attn_v_W [H]
{
    __shared__ float As[16][132];
    __shared__ float Bs[16][68];
    const int tid = threadIdx.x;
    const int m0 = blockIdx.x * 128, n0 = blockIdx.y * 64;

    const int arow = tid >> 1;
    const int ak   = (tid & 1) * 8;
    const float* Aptr = enc + (size_t)(m0 + arow) * Hc + ak;

    const int brow = tid >> 2;
    const int bk   = (tid & 3) * 4;
    const float* Bptr = W + (size_t)(n0 + brow) * (2 * Hc) + Hc + bk;

    const int ty = tid >> 4, tx = tid & 15;
    float acc[8][4] = {};

    for (int k0 = 0; k0 < Hc; k0 += 16) {
        float4 a0 = *(const float4*)(Aptr + k0);
        float4 a1 = *(const float4*)(Aptr + k0 + 4);
        float4 bv = *(const float4*)(Bptr + k0);
        As[ak + 0][arow] = a0.x; As[ak + 1][arow] = a0.y;
        As[ak + 2][arow] = a0.z; As[ak + 3][arow] = a0.w;
        As[ak + 4][arow] = a1.x; As[ak + 5][arow] = a1.y;
        As[ak + 6][arow] = a1.z; As[ak + 7][arow] = a1.w;
        Bs[bk + 0][brow] = bv.x; Bs[bk + 1][brow] = bv.y;
        Bs[bk + 2][brow] = bv.z; Bs[bk + 3][brow] = bv.w;
        __syncthreads();
#pragma unroll
        for (int k = 0; k < 16; k++) {
            float4 aa0 = *(const float4*)&As[k][ty * 8];
            float4 aa1 = *(const float4*)&As[k][ty * 8 + 4];
            float4 bb  = *(const float4*)&Bs[k][tx * 4];
            float ar[8] = {aa0.x, aa0.y, aa0.z, aa0.w, aa1.x, aa1.y, aa1.z, aa1.w};
            float br[4] = {bb.x, bb.y, bb.z, bb.w};
#pragma unroll
            for (int i = 0; i < 8; i++)
#pragma unroll
                for (int j = 0; j < 4; j++)
                    acc[i][j] += ar[i] * br[j];
        }
        __syncthreads();
    }

    // Epilogue: tanh, weight by v, reduce over 64-col block
#pragma unroll
    for (int i = 0; i < 8; i++) {
        int r  = m0 + ty * 8 + i;
        int bb = r & (Bc - 1);
        float s = 0.0f;
#pragma unroll
        for (int j = 0; j < 4; j++) {
            int h = n0 + tx * 4 + j;
            s += tanhf(acc[i][j] + g_hWh[bb * Hc + h]) * vvec[h];
        }
#pragma unroll
        for (int off = 1; off < 16; off <<= 1)
            s += __shfl_xor_sync(0xffffffffu, s, off);
        if (tx == 0)
            g_spart[(size_t)r * NB + blockIdx.y] = s;
    }
}

// ---------------------------------------------------------------------------
// Softmax over seq dim (512) per batch b. Writes attn_weights [s*B + b].
// ---------------------------------------------------------------------------
__global__ __launch_bounds__(256)
void softmax_kernel(float* __restrict__ wout)
{
    __shared__ float sc[Sc];
    __shared__ float red[256];
    const int b = blockIdx.x, tid = threadIdx.x;

    for (int s = tid; s < Sc; s += 256) {
        const float* p = &g_spart[(size_t)(s * Bc + b) * NB];
        float v = 0.0f;
#pragma unroll
        for (int i = 0; i < NB; i++) v += p[i];
        sc[s] = v;
    }
    __syncthreads();

    float m = fmaxf(sc[tid], sc[tid + 256]);
    red[tid] = m;
    __syncthreads();
    for (int st = 128; st > 0; st >>= 1) {
        if (tid < st) red[tid] = fmaxf(red[tid], red[tid + st]);
        __syncthreads();
    }
    float mx = red[0];
    __syncthreads();

    float e0 = expf(sc[tid] - mx);
    float e1 = expf(sc[tid + 256] - mx);
    sc[tid] = e0; sc[tid + 256] = e1;
    red[tid] = e0 + e1;
    __syncthreads();
    for (int st = 128; st > 0; st >>= 1) {
        if (tid < st) red[tid] += red[tid + st];
        __syncthreads();
    }
    float inv = 1.0f / red[0];

    wout[(size_t)tid * Bc + b]        = sc[tid] * inv;
    wout[(size_t)(tid + 256) * Bc + b] = sc[tid + 256] * inv;
}

// ---------------------------------------------------------------------------
// Embedding gather into g_x[:, 0:H]
// ---------------------------------------------------------------------------
__global__ __launch_bounds__(256)
void embed_kernel(const int* __restrict__ input, const float* __restrict__ emb)
{
    const int b = blockIdx.x;
    const int idx = input[b];
    const float4* src = (const float4*)(emb + (size_t)idx * Hc);
    float4* dst = (float4*)(g_x + (size_t)b * 2 * Hc);
    dst[threadIdx.x] = src[threadIdx.x];
}

// ---------------------------------------------------------------------------
// context[b, k] = sum_s w[s,b] * enc[s,b,k]  -> g_x[:, H:2H]
// grid (4, 64): blockIdx.x = k-chunk (256), blockIdx.y = b
// ---------------------------------------------------------------------------
__global__ __launch_bounds__(256)
void context_kernel(const float* __restrict__ enc, const float* __restrict__ wts)
{
    __shared__ float w[Sc];
    const int kc = blockIdx.x, b = blockIdx.y, tid = threadIdx.x;
    w[tid]       = wts[(size_t)tid * Bc + b];
    w[tid + 256] = wts[(size_t)(tid + 256) * Bc + b];
    __syncthreads();

    const int k = kc * 256 + tid;
    const float* p = enc + (size_t)b * Hc + k;
    float acc = 0.0f;
#pragma unroll 8
    for (int s = 0; s < Sc; s++)
        acc += w[s] * p[(size_t)s * (Bc * Hc)];
    g_x[(size_t)b * 2 * Hc + Hc + k] = acc;
}

// ---------------------------------------------------------------------------
// GRU gate combine -> h_new
// ---------------------------------------------------------------------------
__global__ __launch_bounds__(256)
void gru_kernel(const float* __restrict__ hidden, float* __restrict__ hnew)
{
    const int g = blockIdx.x * 256 + threadIdx.x;   // 65536 total
    const int b = g >> 10, h = g & 1023;

    float gir = g_gi[(size_t)h * Bc + b];
    float ghr = g_gh[(size_t)h * Bc + b];
    float giz = g_gi[(size_t)(Hc + h) * Bc + b];
    float ghz = g_gh[(size_t)(Hc + h) * Bc + b];
    float gin = g_gi[(size_t)(2 * Hc + h) * Bc + b];
    float ghn = g_gh[(size_t)(2 * Hc + h) * Bc + b];

    float r = 1.0f / (1.0f + expf(-(gir + ghr)));
    float z = 1.0f / (1.0f + expf(-(giz + ghz)));
    float n = tanhf(gin + r * ghn);
    float hp = hidden[g];
    hnew[g] = (1.0f - z) * n + z * hp;
}

// ---------------------------------------------------------------------------
extern "C" void kernel_launch(void* const* d_in, const int* in_sizes, int n_in,
                              void* d_out, int out_size)
{
    const int*   input    = (const int*)d_in[0];
    const float* hidden   = (const float*)d_in[1];
    const float* enc      = (const float*)d_in[2];
    const float* emb      = (const float*)d_in[3];
    const float* attn_w_W = (const float*)d_in[4];
    const float* attn_w_b = (const float*)d_in[5];
    const float* attn_v_W = (const float*)d_in[6];
    // d_in[7] = attn_v_b : softmax-invariant, skipped
    const float* gru_Wih  = (const float*)d_in[8];
    const float* gru_Whh  = (const float*)d_in[9];
    const float* gru_bih  = (const float*)d_in[10];
    const float* gru_bhh  = (const float*)d_in[11];
    const float* out_W    = (const float*)d_in[12];
    const float* out_b    = (const float*)d_in[13];

    float* out    = (float*)d_out;
    float* logits = out;                       // B*V
    float* hnew   = out + (size_t)Bc * Vc;     // B*H
    float* wts    = hnew + (size_t)Bc * Hc;    // S*B

    float *p_hWh, *p_gx, *p_gi, *p_gh;
    cudaGetSymbolAddress((void**)&p_hWh, g_hWh);
    cudaGetSymbolAddress((void**)&p_gx,  g_x);
    cudaGetSymbolAddress((void**)&p_gi,  g_gi);
    cudaGetSymbolAddress((void**)&p_gh,  g_gh);

    // 1. hWh = hidden @ W_h^T + attn_w_b   [64 x 1024]
    gemm_nt_kernel<<<dim3(1, 16), 256>>>(hidden, Hc, attn_w_W, 2 * Hc,
                                         p_hWh, Hc, Hc, nullptr, attn_w_b, 0);
    // 2. fused attention scores (dominant GEMM + tanh + v-dot)
    attn_score_kernel<<<dim3(SB / 128, NB), 256>>>(enc, attn_w_W, attn_v_W);
    // 3. softmax over seq -> attn_weights (output region 3)
    softmax_kernel<<<Bc, 256>>>(wts);
    // 4. embedding gather + context
    embed_kernel<<<Bc, 256>>>(input, emb);
    context_kernel<<<dim3(4, Bc), 256>>>(enc, wts);
    // 5. GRU input/hidden gate GEMMs
    gemm_nt_kernel<<<dim3(48, 1), 256>>>(gru_Wih, 2 * Hc, p_gx, 2 * Hc,
                                         p_gi, Bc, 2 * Hc, gru_bih, nullptr, 0);
    gemm_nt_kernel<<<dim3(48, 1), 256>>>(gru_Whh, Hc, hidden, Hc,
                                         p_gh, Bc, Hc, gru_bhh, nullptr, 0);
    // 6. gate combine -> h_new (output region 2)
    gru_kernel<<<Bc * Hc / 256, 256>>>(hidden, hnew);
    // 7. logits = h_new @ out_W^T + out_b (output region 1, transposed store)
    gemm_nt_kernel<<<dim3(Vc / 64, 1), 256>>>(out_W, Hc, hnew, Hc,
                                              logits, Vc, Hc, out_b, nullptr, 1);
}

// round 3
// speedup vs baseline: 2.6912x; 2.6912x over previous
#include <cuda_runtime.h>
#include <cstdint>
#include <cstddef>

#define Bc 64
#define Sc 512
#define Hc 1024
#define Vc 32000
#define SB (Sc * Bc)

// ---------------- scratch (device globals, no allocation) ----------------
__device__ float g_hWh[Bc * Hc];        // [b][h] : hidden @ W_h^T + attn_w_b
__device__ float g_spart[SB * 16];      // 16 partial scores per row r = s*B+b
__device__ float g_x[Bc * 2 * Hc];      // [b][emb ; context]
__device__ float g_gi[Bc * 3 * Hc];     // [b][3H]
__device__ float g_gh[Bc * 3 * Hc];     // [b][3H]

// ---------------- portable-PTX tensor-core helpers ----------------
__device__ __forceinline__ uint32_t smem_u32(const void* p) {
    uint32_t a;
    asm("{ .reg .u64 t; cvta.to.shared.u64 t, %1; cvt.u32.u64 %0, t; }"
        : "=r"(a) : "l"(p));
    return a;
}
#define CPA(dst, src) \
    asm volatile("cp.async.cg.shared.global [%0], [%1], 16;" :: "r"(dst), "l"(src))
#define CPCOMMIT() asm volatile("cp.async.commit_group;" ::: "memory")
#define CPWAIT(n)  asm volatile("cp.async.wait_group %0;" :: "n"(n) : "memory")

__device__ __forceinline__ void mma_tf32(float* c, const uint32_t* a, const uint32_t* b) {
    asm volatile(
        "mma.sync.aligned.m16n8k8.row.col.f32.tf32.tf32.f32 "
        "{%0,%1,%2,%3}, {%4,%5,%6,%7}, {%8,%9}, {%0,%1,%2,%3};"
        : "+f"(c[0]), "+f"(c[1]), "+f"(c[2]), "+f"(c[3])
        : "r"(a[0]), "r"(a[1]), "r"(a[2]), "r"(a[3]), "r"(b[0]), "r"(b[1]));
}

// ===========================================================================
// Attention score kernel (mma.sync tf32), CTA tile 128x128.
//  D[m, n] = enc[m0+m, :] . We[n0+n, :]   (We = attn_w_W[:, H:2H])
//  epilogue: partial[r, blk] = sum_{n in 64-col half} tanh(D + hWh[b][n]) * v[n]
//  grid = (8 n-tiles, 256 m-tiles), n fastest for L2 reuse of enc.
// ===========================================================================
__global__ void __launch_bounds__(256, 2)
attn_score_tc(const float* __restrict__ enc, const float* __restrict__ W,
              const float* __restrict__ vvec)
{
    // [2 bufs][ A:128x20 | B:128x20 ] floats = 40960 B; epilogue overlays hWh.
    __shared__ float sm[10240];
    __shared__ float shv[128];
    const int tid = threadIdx.x, lane = tid & 31, wid = tid >> 5;
    const int n0 = blockIdx.x * 128, m0 = blockIdx.y * 128;
    const int wm = (wid & 3) * 32, wn = (wid >> 2) * 64;
    const float* Wp = W + Hc;

    float acc[2][8][4] = {};

    const int lr = tid >> 2, lc = (tid & 3) * 4;
    const float* Ag0 = enc + (size_t)(m0 + lr) * Hc + lc;
    const float* Ag1 = enc + (size_t)(m0 + lr + 64) * Hc + lc;
    const float* Bg0 = Wp + (size_t)(n0 + lr) * (2 * Hc) + lc;
    const float* Bg1 = Wp + (size_t)(n0 + lr + 64) * (2 * Hc) + lc;
    const uint32_t sA0 = smem_u32(&sm[lr * 20 + lc]);
    const uint32_t sA1 = smem_u32(&sm[(lr + 64) * 20 + lc]);
    const uint32_t sB0 = smem_u32(&sm[2560 + lr * 20 + lc]);
    const uint32_t sB1 = smem_u32(&sm[2560 + (lr + 64) * 20 + lc]);

#define A_LOAD(buf, k0)                                     \
    do {                                                    \
        CPA(sA0 + (buf) * 20480, Ag0 + (k0));               \
        CPA(sA1 + (buf) * 20480, Ag1 + (k0));               \
        CPA(sB0 + (buf) * 20480, Bg0 + (k0));               \
        CPA(sB1 + (buf) * 20480, Bg1 + (k0));               \
        CPCOMMIT();                                         \
    } while (0)

    A_LOAD(0, 0);
    const int fr = lane >> 2, fc = lane & 3;

    for (int ks = 0; ks < 64; ks++) {
        const int buf = ks & 1;
        if (ks + 1 < 64) { A_LOAD(buf ^ 1, (ks + 1) * 16); CPWAIT(1); }
        else             { CPWAIT(0); }
        __syncthreads();
        const float* As = &sm[buf * 5120];
        const float* Bs = &sm[buf * 5120 + 2560];
#pragma unroll
        for (int kh = 0; kh < 2; kh++) {
            const int k8 = kh * 8;
            uint32_t a[2][4], b[8][2];
#pragma unroll
            for (int mi = 0; mi < 2; mi++) {
                const float* ap = As + (wm + 16 * mi + fr) * 20 + k8 + fc;
                a[mi][0] = __float_as_uint(ap[0]);
                a[mi][1] = __float_as_uint(ap[160]);
                a[mi][2] = __float_as_uint(ap[4]);
                a[mi][3] = __float_as_uint(ap[164]);
            }
#pragma unroll
            for (int nj = 0; nj < 8; nj++) {
                const float* bp = Bs + (wn + 8 * nj + fr) * 20 + k8 + fc;
                b[nj][0] = __float_as_uint(bp[0]);
                b[nj][1] = __float_as_uint(bp[4]);
            }
#pragma unroll
            for (int mi = 0; mi < 2; mi++)
#pragma unroll
                for (int nj = 0; nj < 8; nj++)
                    mma_tf32(acc[mi][nj], a[mi], b[nj]);
        }
        __syncthreads();
    }
#undef A_LOAD

    // ---- epilogue: stage hWh slice (stride 132) and v slice ----
    for (int j = tid; j < 64 * 128; j += 256) {
        int b = j >> 7, c = j & 127;
        sm[b * 132 + c] = g_hWh[b * Hc + n0 + c];
    }
    if (tid < 128) shv[tid] = vvec[n0 + tid];
    __syncthreads();

    const int c2 = (lane & 3) * 2;
    float s[2][2] = {};
#pragma unroll
    for (int mi = 0; mi < 2; mi++) {
        const int R0 = wm + 16 * mi + fr;
        const int b0r = R0 & 63, b1r = (R0 + 8) & 63;
#pragma unroll
        for (int nj = 0; nj < 8; nj++) {
            const int n = wn + 8 * nj + c2;
            const float v0 = shv[n], v1 = shv[n + 1];
            s[mi][0] += tanhf(acc[mi][nj][0] + sm[b0r * 132 + n]) * v0
                      + tanhf(acc[mi][nj][1] + sm[b0r * 132 + n + 1]) * v1;
            s[mi][1] += tanhf(acc[mi][nj][2] + sm[b1r * 132 + n]) * v0
                      + tanhf(acc[mi][nj][3] + sm[b1r * 132 + n + 1]) * v1;
        }
    }
#pragma unroll
    for (int mi = 0; mi < 2; mi++)
#pragma unroll
        for (int h = 0; h < 2; h++) {
            s[mi][h] += __shfl_xor_sync(0xffffffffu, s[mi][h], 1);
            s[mi][h] += __shfl_xor_sync(0xffffffffu, s[mi][h], 2);
        }
    if ((lane & 3) == 0) {
        const int col = blockIdx.x * 2 + (wid >> 2);
#pragma unroll
        for (int mi = 0; mi < 2; mi++) {
            const int R0 = wm + 16 * mi + fr;
            g_spart[(size_t)(m0 + R0) * 16 + col]     = s[mi][0];
            g_spart[(size_t)(m0 + R0 + 8) * 16 + col] = s[mi][1];
        }
    }
}

// ===========================================================================
// Unified "weight @ activation^T" tf32 kernel (batch side N=64):
//   C[n][m0+m] = sum_k A[m0+m, k] * act[n, k] + bias[m0+m]
//   grid = M/128. Used for hWh, gi, gh, logits.
// ===========================================================================
__global__ void __launch_bounds__(256, 2)
gemm_wact_tc(const float* __restrict__ A, int lda, int K,
             const float* __restrict__ act,
             float* __restrict__ C, int ldc,
             const float* __restrict__ bias)
{
    __shared__ float sm[7680];   // [2 bufs][ A:128x20 | act:64x20 ]
    const int tid = threadIdx.x, lane = tid & 31, wid = tid >> 5;
    const int m0 = blockIdx.x * 128;
    const int wm = (wid & 3) * 32, wn = (wid >> 2) * 32;

    float acc[2][4][4] = {};

    const int lr = tid >> 2, lc = (tid & 3) * 4;
    const float* Ag0 = A + (size_t)(m0 + lr) * lda + lc;
    const float* Ag1 = A + (size_t)(m0 + lr + 64) * lda + lc;
    const float* Cg  = act + (size_t)lr * K + lc;
    const uint32_t sA0 = smem_u32(&sm[lr * 20 + lc]);
    const uint32_t sA1 = smem_u32(&sm[(lr + 64) * 20 + lc]);
    const uint32_t sC0 = smem_u32(&sm[2560 + lr * 20 + lc]);

#define W_LOAD(buf, k0)                                     \
    do {                                                    \
        CPA(sA0 + (buf) * 15360, Ag0 + (k0));               \
        CPA(sA1 + (buf) * 15360, Ag1 + (k0));               \
        CPA(sC0 + (buf) * 15360, Cg + (k0));                \
        CPCOMMIT();                                         \
    } while (0)

    const int NS = K / 16;
    W_LOAD(0, 0);
    const int fr = lane >> 2, fc = lane & 3;

    for (int ks = 0; ks < NS; ks++) {
        const int buf = ks & 1;
        if (ks + 1 < NS) { W_LOAD(buf ^ 1, (ks + 1) * 16); CPWAIT(1); }
        else             { CPWAIT(0); }
        __syncthreads();
        const float* As = &sm[buf * 3840];
        const float* Bs = &sm[buf * 3840 + 2560];
#pragma unroll
        for (int kh = 0; kh < 2; kh++) {
            const int k8 = kh * 8;
            uint32_t a[2][4], b[4][2];
#pragma unroll
            for (int mi = 0; mi < 2; mi++) {
                const float* ap = As + (wm + 16 * mi + fr) * 20 + k8 + fc;
                a[mi][0] = __float_as_uint(ap[0]);
                a[mi][1] = __float_as_uint(ap[160]);
                a[mi][2] = __float_as_uint(ap[4]);
                a[mi][3] = __float_as_uint(ap[164]);
            }
#pragma unroll
            for (int nj = 0; nj < 4; nj++) {
                const float* bp = Bs + (wn + 8 * nj + fr) * 20 + k8 + fc;
                b[nj][0] = __float_as_uint(bp[0]);
                b[nj][1] = __float_as_uint(bp[4]);
            }
#pragma unroll
            for (int mi = 0; mi < 2; mi++)
#pragma unroll
                for (int nj = 0; nj < 4; nj++)
                    mma_tf32(acc[mi][nj], a[mi], b[nj]);
        }
        __syncthreads();
    }
#undef W_LOAD

    const int c2 = (lane & 3) * 2;
#pragma unroll
    for (int mi = 0; mi < 2; mi++) {
        const int m = m0 + wm + 16 * mi + fr;
        const float bm0 = bias[m], bm1 = bias[m + 8];
#pragma unroll
        for (int nj = 0; nj < 4; nj++) {
            const int n = wn + 8 * nj + c2;
            C[(size_t)n * ldc + m]           = acc[mi][nj][0] + bm0;
            C[(size_t)(n + 1) * ldc + m]     = acc[mi][nj][1] + bm0;
            C[(size_t)n * ldc + m + 8]       = acc[mi][nj][2] + bm1;
            C[(size_t)(n + 1) * ldc + m + 8] = acc[mi][nj][3] + bm1;
        }
    }
}

// ===========================================================================
// Softmax over seq (512) per batch. Sums the 16 attention partials.
// ===========================================================================
__global__ void __launch_bounds__(256)
softmax_kernel(float* __restrict__ wout)
{
    __shared__ float sc[Sc];
    __shared__ float red[256];
    const int b = blockIdx.x, tid = threadIdx.x;

    for (int s = tid; s < Sc; s += 256) {
        const float* p = &g_spart[(size_t)(s * Bc + b) * 16];
        float v = 0.0f;
#pragma unroll
        for (int i = 0; i < 16; i++) v += p[i];
        sc[s] = v;
    }
    __syncthreads();

    float m = fmaxf(sc[tid], sc[tid + 256]);
    red[tid] = m;
    __syncthreads();
    for (int st = 128; st > 0; st >>= 1) {
        if (tid < st) red[tid] = fmaxf(red[tid], red[tid + st]);
        __syncthreads();
    }
    float mx = red[0];
    __syncthreads();

    float e0 = expf(sc[tid] - mx);
    float e1 = expf(sc[tid + 256] - mx);
    sc[tid] = e0; sc[tid + 256] = e1;
    red[tid] = e0 + e1;
    __syncthreads();
    for (int st = 128; st > 0; st >>= 1) {
        if (tid < st) red[tid] += red[tid + st];
        __syncthreads();
    }
    float inv = 1.0f / red[0];

    wout[(size_t)tid * Bc + b]         = sc[tid] * inv;
    wout[(size_t)(tid + 256) * Bc + b] = sc[tid + 256] * inv;
}

__global__ void __launch_bounds__(256)
embed_kernel(const int* __restrict__ input, const float* __restrict__ emb)
{
    const int b = blockIdx.x;
    const int idx = input[b];
    const float4* src = (const float4*)(emb + (size_t)idx * Hc);
    float4* dst = (float4*)(g_x + (size_t)b * 2 * Hc);
    dst[threadIdx.x] = src[threadIdx.x];
}

__global__ void __launch_bounds__(256)
context_kernel(const float* __restrict__ enc, const float* __restrict__ wts)
{
    __shared__ float w[Sc];
    const int kc = blockIdx.x, b = blockIdx.y, tid = threadIdx.x;
    w[tid]       = wts[(size_t)tid * Bc + b];
    w[tid + 256] = wts[(size_t)(tid + 256) * Bc + b];
    __syncthreads();

    const int k = kc * 256 + tid;
    const float* p = enc + (size_t)b * Hc + k;
    float acc = 0.0f;
#pragma unroll 8
    for (int s = 0; s < Sc; s++)
        acc += w[s] * p[(size_t)s * (Bc * Hc)];
    g_x[(size_t)b * 2 * Hc + Hc + k] = acc;
}

__global__ void __launch_bounds__(256)
gru_kernel(const float* __restrict__ hidden, float* __restrict__ hnew)
{
    const int g = blockIdx.x * 256 + threadIdx.x;   // 65536
    const int b = g >> 10, h = g & 1023;
    const float* gi = g_gi + (size_t)b * 3 * Hc;
    const float* gh = g_gh + (size_t)b * 3 * Hc;

    float r = 1.0f / (1.0f + expf(-(gi[h] + gh[h])));
    float z = 1.0f / (1.0f + expf(-(gi[Hc + h] + gh[Hc + h])));
    float n = tanhf(gi[2 * Hc + h] + r * gh[2 * Hc + h]);
    float hp = hidden[g];
    hnew[g] = (1.0f - z) * n + z * hp;
}

// ===========================================================================
extern "C" void kernel_launch(void* const* d_in, const int* in_sizes, int n_in,
                              void* d_out, int out_size)
{
    const int*   input    = (const int*)d_in[0];
    const float* hidden   = (const float*)d_in[1];
    const float* enc      = (const float*)d_in[2];
    const float* emb      = (const float*)d_in[3];
    const float* attn_w_W = (const float*)d_in[4];
    const float* attn_w_b = (const float*)d_in[5];
    const float* attn_v_W = (const float*)d_in[6];
    // d_in[7] = attn_v_b : softmax-invariant, skipped
    const float* gru_Wih  = (const float*)d_in[8];
    const float* gru_Whh  = (const float*)d_in[9];
    const float* gru_bih  = (const float*)d_in[10];
    const float* gru_bhh  = (const float*)d_in[11];
    const float* out_W    = (const float*)d_in[12];
    const float* out_b    = (const float*)d_in[13];

    float* out    = (float*)d_out;
    float* logits = out;                        // B*V
    float* hnew   = out + (size_t)Bc * Vc;      // B*H
    float* wts    = hnew + (size_t)Bc * Hc;     // S*B

    float *p_hWh, *p_gx, *p_gi, *p_gh;
    cudaGetSymbolAddress((void**)&p_hWh, g_hWh);
    cudaGetSymbolAddress((void**)&p_gx,  g_x);
    cudaGetSymbolAddress((void**)&p_gi,  g_gi);
    cudaGetSymbolAddress((void**)&p_gh,  g_gh);

    // 1. hWh[b][h] = hidden @ W_h^T + attn_w_b
    gemm_wact_tc<<<8, 256>>>(attn_w_W, 2 * Hc, Hc, hidden, p_hWh, Hc, attn_w_b);
    // 2. fused attention scores (mma.sync tf32 + tanh + v-dot)
    attn_score_tc<<<dim3(8, 256), 256>>>(enc, attn_w_W, attn_v_W);
    // 3. softmax over seq -> attn_weights (output region 3)
    softmax_kernel<<<Bc, 256>>>(wts);
    // 4. embedding gather + context
    embed_kernel<<<Bc, 256>>>(input, emb);
    context_kernel<<<dim3(4, Bc), 256>>>(enc, wts);
    // 5. GRU gate GEMMs (batch-major stores)
    gemm_wact_tc<<<24, 256>>>(gru_Wih, 2 * Hc, 2 * Hc, p_gx, p_gi, 3 * Hc, gru_bih);
    gemm_wact_tc<<<24, 256>>>(gru_Whh, Hc, Hc, hidden, p_gh, 3 * Hc, gru_bhh);
    // 6. gate combine -> h_new (output region 2)
    gru_kernel<<<Bc * Hc / 256, 256>>>(hidden, hnew);
    // 7. logits = h_new @ out_W^T + out_b (output region 1)
    gemm_wact_tc<<<Vc / 128, 256>>>(out_W, Hc, Hc, hnew, logits, Vc, out_b);
}

// round 4
// speedup vs baseline: 3.2236x; 1.1979x over previous
#include <cuda_runtime.h>
#include <cstdint>
#include <cstddef>

#define Bc 64
#define Sc 512
#define Hc 1024
#define Vc 32000
#define SB (Sc * Bc)

// ---------------- scratch (device globals, no allocation) ----------------
__device__ float g_hWh[Bc * Hc];         // reduced: [b][h] hidden@W_h^T + attn_w_b
__device__ float g_hWhp[4 * Bc * Hc];    // split-K partials
__device__ float g_spart[SB * 32];       // 32 partial scores per row r = s*B+b
__device__ float g_x[Bc * 2 * Hc];       // [b][emb ; context]
__device__ float g_gip[4 * Bc * 3 * Hc]; // gi split-K partials [z][b][3H]
__device__ float g_ghp[4 * Bc * 3 * Hc]; // gh split-K partials [z][b][3H]

// ---------------- portable-PTX helpers ----------------
__device__ __forceinline__ uint32_t smem_u32(const void* p) {
    uint32_t a;
    asm("{ .reg .u64 t; cvta.to.shared.u64 t, %1; cvt.u32.u64 %0, t; }"
        : "=r"(a) : "l"(p));
    return a;
}
#define CPA(dst, src) \
    asm volatile("cp.async.cg.shared.global [%0], [%1], 16;" :: "r"(dst), "l"(src))
#define CPCOMMIT() asm volatile("cp.async.commit_group;" ::: "memory")
#define CPWAIT(n)  asm volatile("cp.async.wait_group %0;" :: "n"(n) : "memory")

__device__ __forceinline__ void mma_tf32(float* c, const uint32_t* a, const uint32_t* b) {
    asm volatile(
        "mma.sync.aligned.m16n8k8.row.col.f32.tf32.tf32.f32 "
        "{%0,%1,%2,%3}, {%4,%5,%6,%7}, {%8,%9}, {%0,%1,%2,%3};"
        : "+f"(c[0]), "+f"(c[1]), "+f"(c[2]), "+f"(c[3])
        : "r"(a[0]), "r"(a[1]), "r"(a[2]), "r"(a[3]), "r"(b[0]), "r"(b[1]));
}

// ===========================================================================
// Attention score kernel (mma.sync tf32). CTA tile 128x128, warp tile 64x32,
// K-stage 32, double-buffered cp.async, 2 CTAs/SM.
//  D[m, n] = enc[m0+m, :] . We[n0+n, :]
//  epilogue: partial[r, col] = sum_{n in warp's 32 cols} tanh(D + hWh[b][n]) * v[n]
// ===========================================================================
__global__ void __launch_bounds__(256, 2)
attn_score_tc(const float* __restrict__ enc, const float* __restrict__ W,
              const float* __restrict__ vvec)
{
    extern __shared__ float sm[];   // 2 stages x (A 128x36 + B 128x36) = 73728 B
    const int tid = threadIdx.x, lane = tid & 31, wid = tid >> 5;
    const int n0 = blockIdx.x * 128, m0 = blockIdx.y * 128;
    const int wm = (wid >> 2) * 64, wn = (wid & 3) * 32;
    const float* Wp = W + Hc;
    const uint32_t sbase = smem_u32(sm);

    float acc[4][4][4] = {};

#define LOAD_STAGE(buf, kk)                                                   \
    do {                                                                      \
        const uint32_t db = sbase + (buf) * 36864u;                           \
        _Pragma("unroll")                                                     \
        for (int i_ = 0; i_ < 4; i_++) {                                      \
            int c_ = i_ * 256 + tid;                                          \
            int row_ = c_ >> 3, kc_ = c_ & 7;                                 \
            CPA(db + (row_ * 36 + kc_ * 4) * 4,                               \
                enc + (size_t)(m0 + row_) * Hc + (kk) + kc_ * 4);             \
            CPA(db + 18432u + (row_ * 36 + kc_ * 4) * 4,                      \
                Wp + (size_t)(n0 + row_) * (2 * Hc) + (kk) + kc_ * 4);        \
        }                                                                     \
        CPCOMMIT();                                                           \
    } while (0)

    LOAD_STAGE(0, 0);
    const int fr = lane >> 2, fc = lane & 3;

    for (int ks = 0; ks < 32; ks++) {
        const int buf = ks & 1;
        if (ks < 31) { LOAD_STAGE(buf ^ 1, (ks + 1) * 32); CPWAIT(1); }
        else         { CPWAIT(0); }
        __syncthreads();
        const float* Sa = sm + buf * 9216;
        const float* Sb = Sa + 4608;
#pragma unroll
        for (int kh = 0; kh < 4; kh++) {
            const int k8 = kh * 8;
            uint32_t a[4][4], b[4][2];
#pragma unroll
            for (int mi = 0; mi < 4; mi++) {
                const float* ap = Sa + (wm + 16 * mi + fr) * 36 + k8 + fc;
                a[mi][0] = __float_as_uint(ap[0]);
                a[mi][1] = __float_as_uint(ap[288]);
                a[mi][2] = __float_as_uint(ap[4]);
                a[mi][3] = __float_as_uint(ap[292]);
            }
#pragma unroll
            for (int nj = 0; nj < 4; nj++) {
                const float* bp = Sb + (wn + 8 * nj + fr) * 36 + k8 + fc;
                b[nj][0] = __float_as_uint(bp[0]);
                b[nj][1] = __float_as_uint(bp[4]);
            }
#pragma unroll
            for (int mi = 0; mi < 4; mi++)
#pragma unroll
                for (int nj = 0; nj < 4; nj++)
                    mma_tf32(acc[mi][nj], a[mi], b[nj]);
        }
        __syncthreads();
    }
#undef LOAD_STAGE

    // ---- epilogue: stage hWh slice (stride 133, conflict-free) + v slice ----
    float* shf = sm;
    float* shv = sm + 64 * 133;
    for (int j = tid; j < 64 * 128; j += 256) {
        int b = j >> 7, c = j & 127;
        shf[b * 133 + c] = g_hWh[b * Hc + n0 + c];
    }
    if (tid < 128) shv[tid] = vvec[n0 + tid];
    __syncthreads();

    const int c2 = (lane & 3) * 2;
    float s[4][2] = {};
#pragma unroll
    for (int mi = 0; mi < 4; mi++) {
        const int R0 = wm + 16 * mi + fr;
        const int b0 = R0 & 63, b1 = (R0 + 8) & 63;
#pragma unroll
        for (int nj = 0; nj < 4; nj++) {
            const int n = wn + 8 * nj + c2;
            const float v0 = shv[n], v1 = shv[n + 1];
            s[mi][0] += tanhf(acc[mi][nj][0] + shf[b0 * 133 + n]) * v0
                      + tanhf(acc[mi][nj][1] + shf[b0 * 133 + n + 1]) * v1;
            s[mi][1] += tanhf(acc[mi][nj][2] + shf[b1 * 133 + n]) * v0
                      + tanhf(acc[mi][nj][3] + shf[b1 * 133 + n + 1]) * v1;
        }
    }
#pragma unroll
    for (int mi = 0; mi < 4; mi++)
#pragma unroll
        for (int h = 0; h < 2; h++) {
            s[mi][h] += __shfl_xor_sync(0xffffffffu, s[mi][h], 1);
            s[mi][h] += __shfl_xor_sync(0xffffffffu, s[mi][h], 2);
        }
    if ((lane & 3) == 0) {
        const int col = blockIdx.x * 4 + (wid & 3);
#pragma unroll
        for (int mi = 0; mi < 4; mi++) {
            const int R0 = wm + 16 * mi + fr;
            g_spart[(size_t)(m0 + R0) * 32 + col]     = s[mi][0];
            g_spart[(size_t)(m0 + R0 + 8) * 32 + col] = s[mi][1];
        }
    }
}

// ===========================================================================
// Exact fp32 SIMT split-K GEMM: Cpart[z][n][m] = A[m0+m, zKs:(z+1)Ks] . act[n, zKs:...]
// Tile 64x64, N=64 (batch), grid (M/64, 1, 4).
// ===========================================================================
__global__ void __launch_bounds__(256)
gemm_nt_splitk(const float* __restrict__ A, int lda,
               const float* __restrict__ act, int ldact,
               float* __restrict__ Cpart, int M, int Ks)
{
    __shared__ float As[16][68];
    __shared__ float Bs[16][68];
    const int tid = threadIdx.x;
    const int m0 = blockIdx.x * 64;
    const int z = blockIdx.z;

    const int lrow = tid >> 2, lk = (tid & 3) * 4;
    const float* Ap = A + (size_t)(m0 + lrow) * lda + z * Ks + lk;
    const float* Bp = act + (size_t)lrow * ldact + z * Ks + lk;

    const int ty = tid >> 4, tx = tid & 15;
    float acc[4][4] = {};

    for (int k0 = 0; k0 < Ks; k0 += 16) {
        float4 av = *(const float4*)(Ap + k0);
        float4 bv = *(const float4*)(Bp + k0);
        As[lk + 0][lrow] = av.x; As[lk + 1][lrow] = av.y;
        As[lk + 2][lrow] = av.z; As[lk + 3][lrow] = av.w;
        Bs[lk + 0][lrow] = bv.x; Bs[lk + 1][lrow] = bv.y;
        Bs[lk + 2][lrow] = bv.z; Bs[lk + 3][lrow] = bv.w;
        __syncthreads();
#pragma unroll
        for (int k = 0; k < 16; k++) {
            float4 a = *(const float4*)&As[k][ty * 4];
            float4 b = *(const float4*)&Bs[k][tx * 4];
            float ar[4] = {a.x, a.y, a.z, a.w};
            float br[4] = {b.x, b.y, b.z, b.w};
#pragma unroll
            for (int i = 0; i < 4; i++)
#pragma unroll
                for (int j = 0; j < 4; j++)
                    acc[i][j] += ar[i] * br[j];
        }
        __syncthreads();
    }

#pragma unroll
    for (int i = 0; i < 4; i++)
#pragma unroll
        for (int j = 0; j < 4; j++)
            Cpart[(size_t)(z * 64 + tx * 4 + j) * M + m0 + ty * 4 + i] = acc[i][j];
}

// Reduce hWh partials + attn_w_b -> g_hWh
__global__ void __launch_bounds__(256)
hwh_reduce(const float* __restrict__ awb)
{
    const int idx = blockIdx.x * 256 + threadIdx.x;   // 65536
    const int b = idx >> 10, h = idx & 1023;
    float v = awb[h];
#pragma unroll
    for (int z = 0; z < 4; z++) v += g_hWhp[(size_t)(z * 64 + b) * Hc + h];
    g_hWh[idx] = v;
}

// ===========================================================================
// tf32 "weight @ activation^T" kernel for logits only (batch side N=64).
// ===========================================================================
__global__ void __launch_bounds__(256, 2)
gemm_wact_tc(const float* __restrict__ A, int lda, int K,
             const float* __restrict__ act,
             float* __restrict__ C, int ldc,
             const float* __restrict__ bias)
{
    __shared__ float sm[7680];   // [2 bufs][ A:128x20 | act:64x20 ]
    const int tid = threadIdx.x, lane = tid & 31, wid = tid >> 5;
    const int m0 = blockIdx.x * 128;
    const int wm = (wid & 3) * 32, wn = (wid >> 2) * 32;

    float acc[2][4][4] = {};

    const int lr = tid >> 2, lc = (tid & 3) * 4;
    const float* Ag0 = A + (size_t)(m0 + lr) * lda + lc;
    const float* Ag1 = A + (size_t)(m0 + lr + 64) * lda + lc;
    const float* Cg  = act + (size_t)lr * K + lc;
    const uint32_t sA0 = smem_u32(&sm[lr * 20 + lc]);
    const uint32_t sA1 = smem_u32(&sm[(lr + 64) * 20 + lc]);
    const uint32_t sC0 = smem_u32(&sm[2560 + lr * 20 + lc]);

#define W_LOAD(buf, k0)                                     \
    do {                                                    \
        CPA(sA0 + (buf) * 15360, Ag0 + (k0));               \
        CPA(sA1 + (buf) * 15360, Ag1 + (k0));               \
        CPA(sC0 + (buf) * 15360, Cg + (k0));                \
        CPCOMMIT();                                         \
    } while (0)

    const int NS = K / 16;
    W_LOAD(0, 0);
    const int fr = lane >> 2, fc = lane & 3;

    for (int ks = 0; ks < NS; ks++) {
        const int buf = ks & 1;
        if (ks + 1 < NS) { W_LOAD(buf ^ 1, (ks + 1) * 16); CPWAIT(1); }
        else             { CPWAIT(0); }
        __syncthreads();
        const float* As = &sm[buf * 3840];
        const float* Bs = &sm[buf * 3840 + 2560];
#pragma unroll
        for (int kh = 0; kh < 2; kh++) {
            const int k8 = kh * 8;
            uint32_t a[2][4], b[4][2];
#pragma unroll
            for (int mi = 0; mi < 2; mi++) {
                const float* ap = As + (wm + 16 * mi + fr) * 20 + k8 + fc;
                a[mi][0] = __float_as_uint(ap[0]);
                a[mi][1] = __float_as_uint(ap[160]);
                a[mi][2] = __float_as_uint(ap[4]);
                a[mi][3] = __float_as_uint(ap[164]);
            }
#pragma unroll
            for (int nj = 0; nj < 4; nj++) {
                const float* bp = Bs + (wn + 8 * nj + fr) * 20 + k8 + fc;
                b[nj][0] = __float_as_uint(bp[0]);
                b[nj][1] = __float_as_uint(bp[4]);
            }
#pragma unroll
            for (int mi = 0; mi < 2; mi++)
#pragma unroll
                for (int nj = 0; nj < 4; nj++)
                    mma_tf32(acc[mi][nj], a[mi], b[nj]);
        }
        __syncthreads();
    }
#undef W_LOAD

    const int c2 = (lane & 3) * 2;
#pragma unroll
    for (int mi = 0; mi < 2; mi++) {
        const int m = m0 + wm + 16 * mi + fr;
        const float bm0 = bias[m], bm1 = bias[m + 8];
#pragma unroll
        for (int nj = 0; nj < 4; nj++) {
            const int n = wn + 8 * nj + c2;
            C[(size_t)n * ldc + m]           = acc[mi][nj][0] + bm0;
            C[(size_t)(n + 1) * ldc + m]     = acc[mi][nj][1] + bm0;
            C[(size_t)n * ldc + m + 8]       = acc[mi][nj][2] + bm1;
            C[(size_t)(n + 1) * ldc + m + 8] = acc[mi][nj][3] + bm1;
        }
    }
}

// ===========================================================================
// Softmax over seq (512) per batch. Sums the 32 attention partials.
// ===========================================================================
__global__ void __launch_bounds__(256)
softmax_kernel(float* __restrict__ wout)
{
    __shared__ float sc[Sc];
    __shared__ float red[256];
    const int b = blockIdx.x, tid = threadIdx.x;

    for (int s = tid; s < Sc; s += 256) {
        const float4* p = (const float4*)&g_spart[(size_t)(s * Bc + b) * 32];
        float v = 0.0f;
#pragma unroll
        for (int i = 0; i < 8; i++) {
            float4 q = p[i];
            v += q.x + q.y + q.z + q.w;
        }
        sc[s] = v;
    }
    __syncthreads();

    float m = fmaxf(sc[tid], sc[tid + 256]);
    red[tid] = m;
    __syncthreads();
    for (int st = 128; st > 0; st >>= 1) {
        if (tid < st) red[tid] = fmaxf(red[tid], red[tid + st]);
        __syncthreads();
    }
    float mx = red[0];
    __syncthreads();

    float e0 = expf(sc[tid] - mx);
    float e1 = expf(sc[tid + 256] - mx);
    sc[tid] = e0; sc[tid + 256] = e1;
    red[tid] = e0 + e1;
    __syncthreads();
    for (int st = 128; st > 0; st >>= 1) {
        if (tid < st) red[tid] += red[tid + st];
        __syncthreads();
    }
    float inv = 1.0f / red[0];

    wout[(size_t)tid * Bc + b]         = sc[tid] * inv;
    wout[(size_t)(tid + 256) * Bc + b] = sc[tid + 256] * inv;
}

__global__ void __launch_bounds__(256)
embed_kernel(const int* __restrict__ input, const float* __restrict__ emb)
{
    const int b = blockIdx.x;
    const int idx = input[b];
    const float4* src = (const float4*)(emb + (size_t)idx * Hc);
    float4* dst = (float4*)(g_x + (size_t)b * 2 * Hc);
    dst[threadIdx.x] = src[threadIdx.x];
}

__global__ void __launch_bounds__(256)
context_kernel(const float* __restrict__ enc, const float* __restrict__ wts)
{
    __shared__ float w[Sc];
    const int kc = blockIdx.x, b = blockIdx.y, tid = threadIdx.x;
    w[tid]       = wts[(size_t)tid * Bc + b];
    w[tid + 256] = wts[(size_t)(tid + 256) * Bc + b];
    __syncthreads();

    const int k = kc * 256 + tid;
    const float* p = enc + (size_t)b * Hc + k;
    float acc = 0.0f;
#pragma unroll 8
    for (int s = 0; s < Sc; s++)
        acc += w[s] * p[(size_t)s * (Bc * Hc)];
    g_x[(size_t)b * 2 * Hc + Hc + k] = acc;
}

// GRU gate combine: sums the 4 split-K partials of gi/gh inline (exact fp32).
__global__ void __launch_bounds__(256)
gru_kernel(const float* __restrict__ hidden, float* __restrict__ hnew,
           const float* __restrict__ bih, const float* __restrict__ bhh)
{
    const int g = blockIdx.x * 256 + threadIdx.x;   // 65536
    const int b = g >> 10, h = g & 1023;

    float gir = bih[h],            ghr = bhh[h];
    float giz = bih[Hc + h],       ghz = bhh[Hc + h];
    float gin = bih[2 * Hc + h],   ghn = bhh[2 * Hc + h];
#pragma unroll
    for (int z = 0; z < 4; z++) {
        const float* gi = g_gip + (size_t)(z * 64 + b) * (3 * Hc);
        const float* gh = g_ghp + (size_t)(z * 64 + b) * (3 * Hc);
        gir += gi[h];          ghr += gh[h];
        giz += gi[Hc + h];     ghz += gh[Hc + h];
        gin += gi[2 * Hc + h]; ghn += gh[2 * Hc + h];
    }
    float r = 1.0f / (1.0f + expf(-(gir + ghr)));
    float z = 1.0f / (1.0f + expf(-(giz + ghz)));
    float n = tanhf(gin + r * ghn);
    float hp = hidden[g];
    hnew[g] = (1.0f - z) * n + z * hp;
}

// ===========================================================================
extern "C" void kernel_launch(void* const* d_in, const int* in_sizes, int n_in,
                              void* d_out, int out_size)
{
    const int*   input    = (const int*)d_in[0];
    const float* hidden   = (const float*)d_in[1];
    const float* enc      = (const float*)d_in[2];
    const float* emb      = (const float*)d_in[3];
    const float* attn_w_W = (const float*)d_in[4];
    const float* attn_w_b = (const float*)d_in[5];
    const float* attn_v_W = (const float*)d_in[6];
    // d_in[7] = attn_v_b : softmax-invariant, skipped
    const float* gru_Wih  = (const float*)d_in[8];
    const float* gru_Whh  = (const float*)d_in[9];
    const float* gru_bih  = (const float*)d_in[10];
    const float* gru_bhh  = (const float*)d_in[11];
    const float* out_W    = (const float*)d_in[12];
    const float* out_b    = (const float*)d_in[13];

    float* out    = (float*)d_out;
    float* logits = out;                        // B*V
    float* hnew   = out + (size_t)Bc * Vc;      // B*H
    float* wts    = hnew + (size_t)Bc * Hc;     // S*B

    float *p_hWhp, *p_gx, *p_gip, *p_ghp;
    cudaGetSymbolAddress((void**)&p_hWhp, g_hWhp);
    cudaGetSymbolAddress((void**)&p_gx,   g_x);
    cudaGetSymbolAddress((void**)&p_gip,  g_gip);
    cudaGetSymbolAddress((void**)&p_ghp,  g_ghp);

    cudaFuncSetAttribute(attn_score_tc, cudaFuncAttributeMaxDynamicSharedMemorySize, 73728);

    // 1. hWh split-K partials (exact fp32): W_h = attn_w_W[:, 0:H]
    gemm_nt_splitk<<<dim3(16, 1, 4), 256>>>(attn_w_W, 2 * Hc, hidden, Hc, p_hWhp, Hc, 256);
    // 2. reduce + bias -> g_hWh
    hwh_reduce<<<256, 256>>>(attn_w_b);
    // 3. gh split-K partials (exact fp32), independent of attention
    gemm_nt_splitk<<<dim3(48, 1, 4), 256>>>(gru_Whh, Hc, hidden, Hc, p_ghp, 3 * Hc, 256);
    // 4. fused attention scores (tf32 tensor + tanh + v-dot)   [profiled slot]
    attn_score_tc<<<dim3(8, 256), 256, 73728>>>(enc, attn_w_W, attn_v_W);
    // 5. softmax over seq -> attn_weights (output region 3)
    softmax_kernel<<<Bc, 256>>>(wts);
    // 6. embedding gather
    embed_kernel<<<Bc, 256>>>(input, emb);
    // 7. context (exact fp32)
    context_kernel<<<dim3(4, Bc), 256>>>(enc, wts);
    // 8. gi split-K partials (exact fp32)
    gemm_nt_splitk<<<dim3(48, 1, 4), 256>>>(gru_Wih, 2 * Hc, p_gx, 2 * Hc, p_gip, 3 * Hc, 512);
    // 9. GRU combine (sums partials) -> h_new (output region 2)
    gru_kernel<<<Bc * Hc / 256, 256>>>(hidden, hnew, gru_bih, gru_bhh);
    // 10. logits = h_new @ out_W^T + out_b (tf32, output region 1)
    gemm_wact_tc<<<Vc / 128, 256>>>(out_W, Hc, Hc, hnew, logits, Vc, out_b);
}